// round 4
// baseline (speedup 1.0000x reference)
#include <cuda_runtime.h>
#include <cuda_fp16.h>
#include <cstdint>

// out = softmax(Q@K / 8 + mask) @ V
// q: [B,H,S,D] f32, k: [B,H,D,S] f32 (pre-transposed), v: [B,H,S,D] f32
// mask: [B,1,1,S] f32, out: [B,H,S,D] f32.  B=4 H=16 S=2048 D=64
// fp16 mma.m16n8k16, fp32 accumulate, online softmax.
// R4: __launch_bounds__(128,3) for 3 CTAs/SM; per-mt softmax retirement
//     to shrink live registers (s[mt] -> pa[mt] early).

#define B_ 4
#define H_ 16
#define S_ 2048
#define D_ 64
#define BM 128          // query rows per CTA
#define BN 64           // keys per tile
#define NTHREADS 128
#define KST 72          // smem row stride in halfs (bank-conflict-free ldmatrix)
#define LOG2E 1.4426950408889634f
#define SCALE_L2 (0.125f * LOG2E)

__device__ __forceinline__ uint32_t smem_u32(const void* p) {
    return (uint32_t)__cvta_generic_to_shared(p);
}

__device__ __forceinline__ void ldsm_x4(uint32_t r[4], uint32_t addr) {
    asm volatile("ldmatrix.sync.aligned.m8n8.x4.shared.b16 {%0,%1,%2,%3}, [%4];"
                 : "=r"(r[0]), "=r"(r[1]), "=r"(r[2]), "=r"(r[3]) : "r"(addr));
}
__device__ __forceinline__ void ldsm_x4_t(uint32_t r[4], uint32_t addr) {
    asm volatile("ldmatrix.sync.aligned.m8n8.x4.trans.shared.b16 {%0,%1,%2,%3}, [%4];"
                 : "=r"(r[0]), "=r"(r[1]), "=r"(r[2]), "=r"(r[3]) : "r"(addr));
}
__device__ __forceinline__ void mma16816(float d[4], const uint32_t a[4],
                                         const uint32_t b0, const uint32_t b1) {
    asm volatile(
        "mma.sync.aligned.m16n8k16.row.col.f32.f16.f16.f32 "
        "{%0,%1,%2,%3},{%4,%5,%6,%7},{%8,%9},{%0,%1,%2,%3};"
        : "+f"(d[0]), "+f"(d[1]), "+f"(d[2]), "+f"(d[3])
        : "r"(a[0]), "r"(a[1]), "r"(a[2]), "r"(a[3]), "r"(b0), "r"(b1));
}
__device__ __forceinline__ float ex2(float x) {
    float r;
    asm("ex2.approx.ftz.f32 %0, %1;" : "=f"(r) : "f"(x));
    return r;
}

__global__ void __launch_bounds__(NTHREADS, 3)
attn_kernel(const float* __restrict__ q, const float* __restrict__ k,
            const float* __restrict__ v, const float* __restrict__ mask,
            float* __restrict__ out)
{
    __shared__ __half Qs[BM * KST];   // [128][72]
    __shared__ __half Ks[BN * KST];   // [64][72]  (d-major: [d][t])
    __shared__ __half Vs[BN * KST];   // [64][72]  (t-major: [t][d])

    const int tid  = threadIdx.x;
    const int lane = tid & 31;
    const int warp = tid >> 5;
    const int bh   = blockIdx.y;
    const int b    = bh >> 4;          // H=16
    const int qrow0 = blockIdx.x * BM;

    const float* qbase = q + (size_t)bh * S_ * D_;
    const float* kbase = k + (size_t)bh * D_ * S_;
    const float* vbase = v + (size_t)bh * S_ * D_;
    const float* mbase = mask + (size_t)b * S_;

    // ---- stage Q (f32 -> f16), [row][d], row stride KST ----
#pragma unroll
    for (int i = 0; i < 16; i++) {
        int idx = tid + i * NTHREADS;          // over 128x16 float4s
        int row = idx >> 4;
        int d4  = (idx & 15) * 4;
        float4 t = *reinterpret_cast<const float4*>(
            qbase + (size_t)(qrow0 + row) * D_ + d4);
        __half2 h0 = __floats2half2_rn(t.x, t.y);
        __half2 h1 = __floats2half2_rn(t.z, t.w);
        uint2 u; u.x = *(uint32_t*)&h0; u.y = *(uint32_t*)&h1;
        *reinterpret_cast<uint2*>(&Qs[row * KST + d4]) = u;
    }
    __syncthreads();

    // ---- load Q A-fragments (per warp: rows warp*32 .. +31) ----
    uint32_t qa[2][4][4];
    const int ldrow = lane & 15;
    const int ldcol8 = (lane >> 4) * 8;
#pragma unroll
    for (int mt = 0; mt < 2; mt++)
#pragma unroll
        for (int kt = 0; kt < 4; kt++) {
            uint32_t a = smem_u32(
                &Qs[(warp * 32 + mt * 16 + ldrow) * KST + kt * 16 + ldcol8]);
            ldsm_x4(qa[mt][kt], a);
        }

    float o[2][8][4];
    float mrun[2][2], lrun[2][2];
#pragma unroll
    for (int mt = 0; mt < 2; mt++) {
        mrun[mt][0] = mrun[mt][1] = -1e30f;
        lrun[mt][0] = lrun[mt][1] = 0.0f;
#pragma unroll
        for (int nt = 0; nt < 8; nt++)
#pragma unroll
            for (int j = 0; j < 4; j++) o[mt][nt][j] = 0.0f;
    }

    for (int t0 = 0; t0 < S_; t0 += BN) {
        __syncthreads();   // protect K/V from previous iteration's reads
        // ---- stage K: gmem [d][t] -> smem [d][t] halfs ----
#pragma unroll
        for (int i = 0; i < 8; i++) {
            int idx = tid + i * NTHREADS;      // over 64x16 float4s
            int d  = idx >> 4;
            int t4 = (idx & 15) * 4;
            float4 f = *reinterpret_cast<const float4*>(
                kbase + (size_t)d * S_ + t0 + t4);
            __half2 h0 = __floats2half2_rn(f.x, f.y);
            __half2 h1 = __floats2half2_rn(f.z, f.w);
            uint2 u; u.x = *(uint32_t*)&h0; u.y = *(uint32_t*)&h1;
            *reinterpret_cast<uint2*>(&Ks[d * KST + t4]) = u;
        }
        // ---- stage V: gmem [t][d] -> smem [t][d] halfs ----
#pragma unroll
        for (int i = 0; i < 8; i++) {
            int idx = tid + i * NTHREADS;
            int t  = idx >> 4;
            int d4 = (idx & 15) * 4;
            float4 f = *reinterpret_cast<const float4*>(
                vbase + (size_t)(t0 + t) * D_ + d4);
            __half2 h0 = __floats2half2_rn(f.x, f.y);
            __half2 h1 = __floats2half2_rn(f.z, f.w);
            uint2 u; u.x = *(uint32_t*)&h0; u.y = *(uint32_t*)&h1;
            *reinterpret_cast<uint2*>(&Vs[t * KST + d4]) = u;
        }
        __syncthreads();

        // ---- GEMM1: S = Q @ K (joint over mt: B-fragments reused) ----
        float s[2][8][4];
#pragma unroll
        for (int mt = 0; mt < 2; mt++)
#pragma unroll
            for (int nt = 0; nt < 8; nt++)
#pragma unroll
                for (int j = 0; j < 4; j++) s[mt][nt][j] = 0.0f;

#pragma unroll
        for (int kt = 0; kt < 4; kt++) {
#pragma unroll
            for (int np = 0; np < 4; np++) {
                uint32_t bfr[4];
                uint32_t a = smem_u32(
                    &Ks[(kt * 16 + ldrow) * KST + np * 16 + ldcol8]);
                ldsm_x4_t(bfr, a);
#pragma unroll
                for (int mt = 0; mt < 2; mt++) {
                    mma16816(s[mt][2 * np],     qa[mt][kt], bfr[0], bfr[1]);
                    mma16816(s[mt][2 * np + 1], qa[mt][kt], bfr[2], bfr[3]);
                }
            }
        }

        // ---- mask (shared across mt) ----
        float mk0[8], mk1[8];
#pragma unroll
        for (int nt = 0; nt < 8; nt++) {
            float2 mv = *reinterpret_cast<const float2*>(
                mbase + t0 + nt * 8 + 2 * (lane & 3));
            mk0[nt] = mv.x * LOG2E;
            mk1[nt] = mv.y * LOG2E;
        }

        // ---- per-mt: softmax then immediately pack s[mt] -> pa[mt] ----
        uint32_t pa[2][4][4];
#pragma unroll
        for (int mt = 0; mt < 2; mt++) {
#pragma unroll
            for (int nt = 0; nt < 8; nt++) {
                s[mt][nt][0] = s[mt][nt][0] * SCALE_L2 + mk0[nt];
                s[mt][nt][1] = s[mt][nt][1] * SCALE_L2 + mk1[nt];
                s[mt][nt][2] = s[mt][nt][2] * SCALE_L2 + mk0[nt];
                s[mt][nt][3] = s[mt][nt][3] * SCALE_L2 + mk1[nt];
            }
#pragma unroll
            for (int h = 0; h < 2; h++) {   // row r (h=0) / r+8 (h=1)
                const int j0 = 2 * h;
                float mx = -1e30f;
#pragma unroll
                for (int nt = 0; nt < 8; nt++)
                    mx = fmaxf(mx, fmaxf(s[mt][nt][j0], s[mt][nt][j0 + 1]));
                mx = fmaxf(mx, __shfl_xor_sync(0xffffffffu, mx, 1));
                mx = fmaxf(mx, __shfl_xor_sync(0xffffffffu, mx, 2));

                float mnew = fmaxf(mrun[mt][h], mx);
                float corr = ex2(mrun[mt][h] - mnew);
                mrun[mt][h] = mnew;

                float psum = 0.0f;
#pragma unroll
                for (int nt = 0; nt < 8; nt++) {
                    float p0 = ex2(s[mt][nt][j0] - mnew);
                    float p1 = ex2(s[mt][nt][j0 + 1] - mnew);
                    s[mt][nt][j0] = p0;
                    s[mt][nt][j0 + 1] = p1;
                    psum += p0 + p1;
                }
                psum += __shfl_xor_sync(0xffffffffu, psum, 1);
                psum += __shfl_xor_sync(0xffffffffu, psum, 2);
                lrun[mt][h] = lrun[mt][h] * corr + psum;
#pragma unroll
                for (int nt = 0; nt < 8; nt++) {
                    o[mt][nt][j0] *= corr;
                    o[mt][nt][j0 + 1] *= corr;
                }
            }
            // pack P (this mt) into A-fragments; s[mt] dies here
#pragma unroll
            for (int kt = 0; kt < 4; kt++) {
                __half2 h;
                h = __floats2half2_rn(s[mt][2 * kt][0], s[mt][2 * kt][1]);
                pa[mt][kt][0] = *(uint32_t*)&h;
                h = __floats2half2_rn(s[mt][2 * kt][2], s[mt][2 * kt][3]);
                pa[mt][kt][1] = *(uint32_t*)&h;
                h = __floats2half2_rn(s[mt][2 * kt + 1][0], s[mt][2 * kt + 1][1]);
                pa[mt][kt][2] = *(uint32_t*)&h;
                h = __floats2half2_rn(s[mt][2 * kt + 1][2], s[mt][2 * kt + 1][3]);
                pa[mt][kt][3] = *(uint32_t*)&h;
            }
        }

        // ---- GEMM2: O += P @ V (joint over mt: B-fragments reused) ----
#pragma unroll
        for (int kt = 0; kt < 4; kt++) {
#pragma unroll
            for (int np = 0; np < 4; np++) {
                uint32_t bfr[4];
                uint32_t a = smem_u32(
                    &Vs[(kt * 16 + ldrow) * KST + np * 16 + ldcol8]);
                ldsm_x4_t(bfr, a);
#pragma unroll
                for (int mt = 0; mt < 2; mt++) {
                    mma16816(o[mt][2 * np],     pa[mt][kt], bfr[0], bfr[1]);
                    mma16816(o[mt][2 * np + 1], pa[mt][kt], bfr[2], bfr[3]);
                }
            }
        }
    }

    // ---- epilogue: normalize & store f32 ----
#pragma unroll
    for (int mt = 0; mt < 2; mt++)
#pragma unroll
        for (int h = 0; h < 2; h++) {
            float inv = 1.0f / lrun[mt][h];
            int row = qrow0 + warp * 32 + mt * 16 + (lane >> 2) + 8 * h;
#pragma unroll
            for (int nt = 0; nt < 8; nt++) {
                float2 res;
                res.x = o[mt][nt][2 * h] * inv;
                res.y = o[mt][nt][2 * h + 1] * inv;
                *reinterpret_cast<float2*>(
                    out + ((size_t)bh * S_ + row) * D_ + nt * 8 + 2 * (lane & 3)) = res;
            }
        }
}

extern "C" void kernel_launch(void* const* d_in, const int* in_sizes, int n_in,
                              void* d_out, int out_size)
{
    const float* q    = (const float*)d_in[0];
    const float* k    = (const float*)d_in[1];
    const float* v    = (const float*)d_in[2];
    const float* mask = (const float*)d_in[3];
    float* out        = (float*)d_out;

    dim3 grid(S_ / BM, B_ * H_);
    attn_kernel<<<grid, NTHREADS>>>(q, k, v, mask, out);
}